// round 6
// baseline (speedup 1.0000x reference)
#include <cuda_runtime.h>
#include <cuda_bf16.h>

#define NN 100000
#define NE 1600000
#define HF 64
#define FULL 0xFFFFFFFFu

#define SB   512
#define NBLK ((NN + SB - 1) / SB)   // 196

// ---------------- scratch (device globals; no allocation allowed) ----------
__device__ float g_h  [NN * HF];
__device__ float g_nf [NN * HF];
__device__ float g_nf2[NN * HF];
__device__ float g_el [NN];
__device__ float g_er [NN];
// CSR-by-dst
__device__ int g_cnt   [NN];
__device__ int g_incl  [NN];
__device__ int g_bsum  [NBLK];
__device__ int g_boff  [NBLK];
__device__ int g_rowptr[NN + 1];
__device__ int g_cursor[NN];
__device__ int g_csrc  [NE];

// ============================ CSR build =====================================
__global__ void csr_zero(int* __restrict__ cnt) {
    int i = blockIdx.x * blockDim.x + threadIdx.x;
    if (i < NN) cnt[i] = 0;
}

__global__ void csr_hist(const int* __restrict__ dst, int* __restrict__ cnt) {
    int e = blockIdx.x * blockDim.x + threadIdx.x;
    if (e < NE) atomicAdd(&cnt[dst[e]], 1);
}

__global__ void csr_scan1(const int* __restrict__ cnt, int* __restrict__ incl,
                          int* __restrict__ bsum) {
    __shared__ int wsum[16];
    int tid = threadIdx.x, lane = tid & 31, wid = tid >> 5;
    int i = blockIdx.x * SB + tid;
    int v = (i < NN) ? cnt[i] : 0;
    int x = v;
    #pragma unroll
    for (int o = 1; o < 32; o <<= 1) {
        int t = __shfl_up_sync(FULL, x, o);
        if (lane >= o) x += t;
    }
    if (lane == 31) wsum[wid] = x;
    __syncthreads();
    if (wid == 0) {
        int w = (lane < 16) ? wsum[lane] : 0;
        #pragma unroll
        for (int o = 1; o < 16; o <<= 1) {
            int t = __shfl_up_sync(FULL, w, o);
            if (lane >= o) w += t;
        }
        if (lane < 16) wsum[lane] = w;
    }
    __syncthreads();
    int inc = x + (wid > 0 ? wsum[wid - 1] : 0);
    if (i < NN) incl[i] = inc;
    if (tid == SB - 1) bsum[blockIdx.x] = inc;
}

__global__ void csr_scan2(const int* __restrict__ bsum, int* __restrict__ boff) {
    __shared__ int wsum[8];
    int tid = threadIdx.x, lane = tid & 31, wid = tid >> 5;
    int v = (tid < NBLK) ? bsum[tid] : 0;
    int x = v;
    #pragma unroll
    for (int o = 1; o < 32; o <<= 1) {
        int t = __shfl_up_sync(FULL, x, o);
        if (lane >= o) x += t;
    }
    if (lane == 31) wsum[wid] = x;
    __syncthreads();
    if (wid == 0) {
        int w = (lane < 8) ? wsum[lane] : 0;
        #pragma unroll
        for (int o = 1; o < 8; o <<= 1) {
            int t = __shfl_up_sync(FULL, w, o);
            if (lane >= o) w += t;
        }
        if (lane < 8) wsum[lane] = w;
    }
    __syncthreads();
    int inc = x + (wid > 0 ? wsum[wid - 1] : 0);
    if (tid < NBLK) boff[tid] = inc - v;
}

__global__ void csr_scan3(const int* __restrict__ cnt, const int* __restrict__ incl,
                          const int* __restrict__ boff, int* __restrict__ rowptr,
                          int* __restrict__ cursor) {
    int b = blockIdx.x;
    int i = b * SB + threadIdx.x;
    if (i < NN) {
        int ex = incl[i] - cnt[i] + boff[b];
        rowptr[i] = ex;
        cursor[i] = ex;
    }
    if (i == 0) rowptr[NN] = NE;
}

__global__ void csr_fill(const int* __restrict__ src, const int* __restrict__ dst,
                         int* __restrict__ cursor, int* __restrict__ csrc) {
    int e = blockIdx.x * blockDim.x + threadIdx.x;
    if (e >= NE) return;
    int p = atomicAdd(&cursor[dst[e]], 1);
    csrc[p] = src[e];
}

// ============================ GEMM (+ el/er) ================================
// 128x64 output tile per 256-thread block; each thread computes an 8x4 subtile.
// x staged TRANSPOSED (sxT[k][row]) so the main loop is 3x LDS.128 -> 32 FMA.
// Pitch 128 is conflict-free here: stores stride 4B across lanes, reads have
// only 2 distinct addresses per warp (broadcast). smem = 32KB + 16KB = 48KB.
#define GR 128            // rows per block
#define XP 128            // sxT row pitch
template <int K>
__global__ void __launch_bounds__(256)
gemm_el_er(const float* __restrict__ x, const float* __restrict__ W,
           const float* __restrict__ al, const float* __restrict__ ar,
           float* __restrict__ h, float* __restrict__ el, float* __restrict__ er) {
    __shared__ float sxT[64][XP];
    __shared__ float sW [64][64];

    int tid = threadIdx.x;
    int base = blockIdx.x * GR;
    int tx = tid & 15, ty = tid >> 4;
    int c0 = tx * 4, r0 = ty * 8;

    float acc[8][4];
    #pragma unroll
    for (int j = 0; j < 8; j++)
        #pragma unroll
        for (int q = 0; q < 4; q++) acc[j][q] = 0.0f;

    for (int kc = 0; kc < K; kc += 64) {
        if (kc) __syncthreads();
        // stage x transposed: thread i handles row r=i&127, k-group q=i>>7
        #pragma unroll
        for (int i = tid; i < GR * 16; i += 256) {
            int r = i & (GR - 1), q = i >> 7;
            int row = base + r;
            float4 v = make_float4(0.f, 0.f, 0.f, 0.f);
            if (row < NN) v = *(const float4*)&x[row * K + kc + q * 4];
            sxT[q * 4 + 0][r] = v.x;
            sxT[q * 4 + 1][r] = v.y;
            sxT[q * 4 + 2][r] = v.z;
            sxT[q * 4 + 3][r] = v.w;
        }
        // stage W
        #pragma unroll
        for (int i = tid; i < 64 * 16; i += 256) {
            int k = i >> 4, q = i & 15;
            *(float4*)&sW[k][q * 4] = *(const float4*)&W[(kc + k) * HF + q * 4];
        }
        __syncthreads();

        #pragma unroll 4
        for (int k = 0; k < 64; k++) {
            float4 w4 = *(const float4*)&sW[k][c0];
            float4 xa = *(const float4*)&sxT[k][r0];
            float4 xb = *(const float4*)&sxT[k][r0 + 4];
            float xv[8] = {xa.x, xa.y, xa.z, xa.w, xb.x, xb.y, xb.z, xb.w};
            #pragma unroll
            for (int j = 0; j < 8; j++) {
                acc[j][0] = fmaf(xv[j], w4.x, acc[j][0]);
                acc[j][1] = fmaf(xv[j], w4.y, acc[j][1]);
                acc[j][2] = fmaf(xv[j], w4.z, acc[j][2]);
                acc[j][3] = fmaf(xv[j], w4.w, acc[j][3]);
            }
        }
    }

    float4 al4 = *(const float4*)&al[c0];
    float4 ar4 = *(const float4*)&ar[c0];
    #pragma unroll
    for (int j = 0; j < 8; j++) {
        int g = base + r0 + j;
        bool ok = g < NN;
        if (ok) *(float4*)&h[g * HF + c0] =
            make_float4(acc[j][0], acc[j][1], acc[j][2], acc[j][3]);
        float pel = acc[j][0] * al4.x + acc[j][1] * al4.y
                  + acc[j][2] * al4.z + acc[j][3] * al4.w;
        float per = acc[j][0] * ar4.x + acc[j][1] * ar4.y
                  + acc[j][2] * ar4.z + acc[j][3] * ar4.w;
        #pragma unroll
        for (int o = 8; o > 0; o >>= 1) {   // reduce over the 16 tx lanes
            pel += __shfl_xor_sync(FULL, pel, o);
            per += __shfl_xor_sync(FULL, per, o);
        }
        if (tx == 0 && ok) { el[g] = pel; er[g] = per; }
    }
}

// ============== fused per-node softmax + aggregate + bias + relu ============
__global__ void __launch_bounds__(256)
gat_aggregate(const int* __restrict__ rowptr, const int* __restrict__ csrc,
              const float* __restrict__ el, const float* __restrict__ er,
              const float* __restrict__ h, const float* __restrict__ b,
              float* __restrict__ y) {
    int gwarp = (blockIdx.x * blockDim.x + threadIdx.x) >> 5;
    if (gwarp >= NN) return;
    int lane = threadIdx.x & 31;

    int beg = rowptr[gwarp], end = rowptr[gwarp + 1];
    float erd = er[gwarp];

    float m = -__int_as_float(0x7F800000);
    float s = 0.0f;
    float a0A = 0.0f, a1A = 0.0f, a0B = 0.0f, a1B = 0.0f;
    int c = 2 * lane;

    for (int base = beg; base < end; base += 32) {
        int idx = base + lane;
        bool valid = idx < end;
        int sn = valid ? csrc[idx] : 0;
        float v;
        if (valid) {
            v = el[sn] + erd;
            v = v > 0.0f ? v : 0.2f * v;
        } else {
            v = -__int_as_float(0x7F800000);
        }
        float gm = v;
        #pragma unroll
        for (int o = 16; o > 0; o >>= 1)
            gm = fmaxf(gm, __shfl_xor_sync(FULL, gm, o));
        float mnew = fmaxf(m, gm);
        float scale = __expf(m - mnew);
        s *= scale; a0A *= scale; a1A *= scale; a0B *= scale; a1B *= scale;
        m = mnew;

        float w = valid ? __expf(v - mnew) : 0.0f;
        float ws = w;
        #pragma unroll
        for (int o = 16; o > 0; o >>= 1)
            ws += __shfl_xor_sync(FULL, ws, o);
        s += ws;

        int cnt = end - base; if (cnt > 32) cnt = 32;
        int j = 0;
        #pragma unroll 2
        for (; j + 1 < cnt; j += 2) {
            int   s0 = __shfl_sync(FULL, sn, j);
            float w0 = __shfl_sync(FULL, w,  j);
            int   s1 = __shfl_sync(FULL, sn, j + 1);
            float w1 = __shfl_sync(FULL, w,  j + 1);
            float2 h0 = *(const float2*)&h[s0 * HF + c];
            float2 h1 = *(const float2*)&h[s1 * HF + c];
            a0A = fmaf(w0, h0.x, a0A); a1A = fmaf(w0, h0.y, a1A);
            a0B = fmaf(w1, h1.x, a0B); a1B = fmaf(w1, h1.y, a1B);
        }
        if (j < cnt) {
            int   s0 = __shfl_sync(FULL, sn, j);
            float w0 = __shfl_sync(FULL, w,  j);
            float2 h0 = *(const float2*)&h[s0 * HF + c];
            a0A = fmaf(w0, h0.x, a0A); a1A = fmaf(w0, h0.y, a1A);
        }
    }

    float inv = (end > beg) ? __fdividef(1.0f, s) : 0.0f;
    float o0 = (a0A + a0B) * inv + b[c];
    float o1 = (a1A + a1B) * inv + b[c + 1];
    o0 = o0 > 0.0f ? o0 : 0.0f;
    o1 = o1 > 0.0f ? o1 : 0.0f;
    *(float2*)&y[gwarp * HF + c] = make_float2(o0, o1);
}

// ============================ host driver ===================================
extern "C" void kernel_launch(void* const* d_in, const int* in_sizes, int n_in,
                              void* d_out, int out_size) {
    const float* x   = (const float*)d_in[0];
    const int*   src = (const int*)  d_in[1];
    const int*   dst = (const int*)  d_in[2];
    const float* W1  = (const float*)d_in[3];
    const float* al1 = (const float*)d_in[4];
    const float* ar1 = (const float*)d_in[5];
    const float* b1  = (const float*)d_in[6];
    const float* W2  = (const float*)d_in[7];
    const float* al2 = (const float*)d_in[8];
    const float* ar2 = (const float*)d_in[9];
    const float* b2  = (const float*)d_in[10];
    const float* W3  = (const float*)d_in[11];
    const float* al3 = (const float*)d_in[12];
    const float* ar3 = (const float*)d_in[13];
    const float* b3  = (const float*)d_in[14];
    float* out = (float*)d_out;

    float *h, *nf, *nf2, *el, *er;
    int *cnt, *incl, *bsum, *boff, *rowptr, *cursor, *csrc;
    cudaGetSymbolAddress((void**)&h,      g_h);
    cudaGetSymbolAddress((void**)&nf,     g_nf);
    cudaGetSymbolAddress((void**)&nf2,    g_nf2);
    cudaGetSymbolAddress((void**)&el,     g_el);
    cudaGetSymbolAddress((void**)&er,     g_er);
    cudaGetSymbolAddress((void**)&cnt,    g_cnt);
    cudaGetSymbolAddress((void**)&incl,   g_incl);
    cudaGetSymbolAddress((void**)&bsum,   g_bsum);
    cudaGetSymbolAddress((void**)&boff,   g_boff);
    cudaGetSymbolAddress((void**)&rowptr, g_rowptr);
    cudaGetSymbolAddress((void**)&cursor, g_cursor);
    cudaGetSymbolAddress((void**)&csrc,   g_csrc);

    static cudaStream_t s2 = nullptr;
    static cudaEvent_t evFork = nullptr, evJoin = nullptr;
    if (!s2) {
        cudaStreamCreateWithFlags(&s2, cudaStreamNonBlocking);
        cudaEventCreateWithFlags(&evFork, cudaEventDisableTiming);
        cudaEventCreateWithFlags(&evJoin, cudaEventDisableTiming);
    }

    // ---- fork: CSR build on s2, layer-1 GEMM on main stream ----
    cudaEventRecord(evFork, 0);
    cudaStreamWaitEvent(s2, evFork, 0);
    csr_zero<<<(NN + 255) / 256, 256, 0, s2>>>(cnt);
    csr_hist<<<(NE + 255) / 256, 256, 0, s2>>>(dst, cnt);
    csr_scan1<<<NBLK, SB, 0, s2>>>(cnt, incl, bsum);
    csr_scan2<<<1, 256, 0, s2>>>(bsum, boff);
    csr_scan3<<<NBLK, SB, 0, s2>>>(cnt, incl, boff, rowptr, cursor);
    csr_fill<<<(NE + 255) / 256, 256, 0, s2>>>(src, dst, cursor, csrc);
    cudaEventRecord(evJoin, s2);

    gemm_el_er<128><<<(NN + GR - 1) / GR, 256>>>(x, W1, al1, ar1, h, el, er);

    cudaStreamWaitEvent(0, evJoin, 0);

    gat_aggregate<<<(NN * 32 + 255) / 256, 256>>>(rowptr, csrc, el, er, h, b1, nf);

    gemm_el_er<64><<<(NN + GR - 1) / GR, 256>>>(nf, W2, al2, ar2, h, el, er);
    gat_aggregate<<<(NN * 32 + 255) / 256, 256>>>(rowptr, csrc, el, er, h, b2, nf2);

    gemm_el_er<64><<<(NN + GR - 1) / GR, 256>>>(nf2, W3, al3, ar3, h, el, er);
    gat_aggregate<<<(NN * 32 + 255) / 256, 256>>>(rowptr, csrc, el, er, h, b3, out);
}